// round 1
// baseline (speedup 1.0000x reference)
#include <cuda_runtime.h>
#include <math.h>

#define NB 2
#define S_LEN 2048
#define D_DIM 2048
#define NH 16
#define DHD 128
#define M_ROWS (NB * S_LEN)   // 4096

// Scratch (rule-compliant: __device__ globals, zero-init .bss)
__device__ float g_Q[NB * S_LEN * D_DIM];
__device__ float g_K[NB * S_LEN * D_DIM];
__device__ float g_V[NB * S_LEN * D_DIM];
__device__ float g_AO[NB * S_LEN * D_DIM];

// ---------------------------------------------------------------------------
// GEMM: Y[M,N] = X[M,K] @ W[N,K]^T + bias[N]   (torch Linear convention)
// 128x128 tile, BK=16, 256 threads, 8x8 per-thread register tile.
// ---------------------------------------------------------------------------
#define BM 128
#define BN 128
#define BKK 16
#define APITCH 132   // pad to reduce STS conflicts; 132*4B is 16B-aligned

__global__ __launch_bounds__(256) void gemm_xwt(
    const float* __restrict__ X, const float* __restrict__ W,
    const float* __restrict__ bias, float* __restrict__ Y,
    int M, int N, int K)
{
    __shared__ float As[BKK * APITCH];
    __shared__ float Bs[BKK * APITCH];

    const int tid = threadIdx.x;
    const int tx = tid & 15;       // 0..15  (N dir)
    const int ty = tid >> 4;       // 0..15  (M dir)
    const int row0 = blockIdx.y * BM;
    const int col0 = blockIdx.x * BN;

    float acc[8][8];
#pragma unroll
    for (int i = 0; i < 8; i++)
#pragma unroll
        for (int j = 0; j < 8; j++) acc[i][j] = 0.0f;

    for (int k0 = 0; k0 < K; k0 += BKK) {
        // load tiles (A transposed into [k][m], B into [k][n])
#pragma unroll
        for (int it = 0; it < 2; it++) {
            int f  = tid + it * 256;       // 0..511 float4 slots
            int r  = f >> 2;               // 0..127 row within tile
            int c4 = (f & 3) << 2;         // 0,4,8,12 : k offset within tile
            float4 va = *(const float4*)&X[(size_t)(row0 + r) * K + k0 + c4];
            As[(c4 + 0) * APITCH + r] = va.x;
            As[(c4 + 1) * APITCH + r] = va.y;
            As[(c4 + 2) * APITCH + r] = va.z;
            As[(c4 + 3) * APITCH + r] = va.w;
            float4 vb = *(const float4*)&W[(size_t)(col0 + r) * K + k0 + c4];
            Bs[(c4 + 0) * APITCH + r] = vb.x;
            Bs[(c4 + 1) * APITCH + r] = vb.y;
            Bs[(c4 + 2) * APITCH + r] = vb.z;
            Bs[(c4 + 3) * APITCH + r] = vb.w;
        }
        __syncthreads();

#pragma unroll
        for (int kk = 0; kk < BKK; kk++) {
            float a[8], b[8];
            *(float4*)(a)     = *(float4*)&As[kk * APITCH + ty * 8];
            *(float4*)(a + 4) = *(float4*)&As[kk * APITCH + ty * 8 + 4];
            *(float4*)(b)     = *(float4*)&Bs[kk * APITCH + tx * 8];
            *(float4*)(b + 4) = *(float4*)&Bs[kk * APITCH + tx * 8 + 4];
#pragma unroll
            for (int i = 0; i < 8; i++)
#pragma unroll
                for (int j = 0; j < 8; j++)
                    acc[i][j] += a[i] * b[j];
        }
        __syncthreads();
    }

    // epilogue with bias
#pragma unroll
    for (int i = 0; i < 8; i++) {
        int gr = row0 + ty * 8 + i;
#pragma unroll
        for (int j4 = 0; j4 < 8; j4 += 4) {
            int gc = col0 + tx * 8 + j4;
            float4 o;
            o.x = acc[i][j4 + 0] + bias[gc + 0];
            o.y = acc[i][j4 + 1] + bias[gc + 1];
            o.z = acc[i][j4 + 2] + bias[gc + 2];
            o.w = acc[i][j4 + 3] + bias[gc + 3];
            *(float4*)&Y[(size_t)gr * N + gc] = o;
        }
    }
}

// ---------------------------------------------------------------------------
// Flash attention (causal), fp32. One block = 64-query tile for one (b,h).
// Q,K kept transposed [d][r] with XOR swizzle for conflict-free access.
// ---------------------------------------------------------------------------
#define QTILE 64
#define KTILE 64
#define SPITCH 65

__device__ __forceinline__ int swz(int d, int cg) {
    // element index of 4-float group cg (0..15) in row d of a [128][64] tile
    return d * 64 + (((cg) ^ (d & 15)) << 2);
}

// dynamic smem layout (floats):
//   QT   128*64  = 8192
//   KT   128*64  = 8192
//   VS    64*128 = 8192
//   SS    64*65  = 4160
//   m,l,sc 3*64  = 192
#define ATTN_SMEM_FLOATS (8192 + 8192 + 8192 + 4160 + 192)
#define ATTN_SMEM_BYTES (ATTN_SMEM_FLOATS * 4)

__global__ __launch_bounds__(256) void flash_attn(const int* __restrict__ maskp)
{
    extern __shared__ float sm[];
    float* QT  = sm;
    float* KT  = QT + 8192;
    float* VS  = KT + 8192;
    float* SS  = VS + 8192;
    float* m_s = SS + 64 * SPITCH;
    float* l_s = m_s + 64;
    float* sc_s = l_s + 64;

    const int tid = threadIdx.x;
    const int tr = tid >> 4;   // 0..15
    const int tc = tid & 15;   // 0..15
    const int qt = blockIdx.x;
    const int h  = blockIdx.y;
    const int b  = blockIdx.z;
    const int q0 = qt * QTILE;

    const float* Qg = g_Q + (size_t)b * S_LEN * D_DIM + h * DHD;
    const float* Kg = g_K + (size_t)b * S_LEN * D_DIM + h * DHD;
    const float* Vg = g_V + (size_t)b * S_LEN * D_DIM + h * DHD;

    // load Q tile transposed+swizzled: QT[swz(d, r>>2)+(r&3)] = Q[q0+r][d]
    for (int f = tid; f < QTILE * DHD; f += 256) {
        int r = f >> 7, d = f & 127;  // consecutive tid -> consecutive d (coalesced)
        QT[swz(d, r >> 2) + (r & 3)] = Qg[(size_t)(q0 + r) * D_DIM + d];
    }
    if (tid < 64) { m_s[tid] = -1e30f; l_s[tid] = 0.0f; }

    float acco[4][8];
#pragma unroll
    for (int i = 0; i < 4; i++)
#pragma unroll
        for (int j = 0; j < 8; j++) acco[i][j] = 0.0f;

    const int causal = maskp[0];
    const int ktmax = causal ? qt : (S_LEN / KTILE - 1);
    const float isq = 0.08838834764831845f;  // 1/sqrt(128)

    for (int kt = 0; kt <= ktmax; kt++) {
        const int k0 = kt * KTILE;
        __syncthreads();  // protect KT/VS/SS from previous iteration readers

        // load K transposed+swizzled (scalar, coalesced gmem, conflict-lite sts)
        for (int f = tid; f < KTILE * DHD; f += 256) {
            int r = f >> 7, d = f & 127;
            KT[swz(d, r >> 2) + (r & 3)] = Kg[(size_t)(k0 + r) * D_DIM + d];
        }
        // load V normal layout [k][d], float4
        for (int f = tid; f < KTILE * (DHD / 4); f += 256) {
            int r = f >> 5, d4 = (f & 31) << 2;
            *(float4*)&VS[r * DHD + d4] =
                *(const float4*)&Vg[(size_t)(k0 + r) * D_DIM + d4];
        }
        __syncthreads();

        // S = Q K^T  (4x4 per thread)
        float accs[4][4];
#pragma unroll
        for (int i = 0; i < 4; i++)
#pragma unroll
            for (int j = 0; j < 4; j++) accs[i][j] = 0.0f;

#pragma unroll 4
        for (int d = 0; d < DHD; d++) {
            float aq[4], bk[4];
            *(float4*)aq = *(float4*)&QT[swz(d, tr)];
            *(float4*)bk = *(float4*)&KT[swz(d, tc)];
#pragma unroll
            for (int i = 0; i < 4; i++)
#pragma unroll
                for (int j = 0; j < 4; j++)
                    accs[i][j] += aq[i] * bk[j];
        }

        // scale + causal mask + store to SS
#pragma unroll
        for (int i = 0; i < 4; i++) {
            int gq = q0 + tr * 4 + i;
#pragma unroll
            for (int j = 0; j < 4; j++) {
                int gk = k0 + tc * 4 + j;
                float s = accs[i][j] * isq;
                if (causal && gk > gq) s = -1e30f;
                SS[(tr * 4 + i) * SPITCH + tc * 4 + j] = s;
            }
        }
        __syncthreads();

        // online softmax row pass (one thread per row)
        if (tid < 64) {
            const int r = tid;
            float mo = m_s[r];
            float mt = mo;
#pragma unroll 8
            for (int k = 0; k < KTILE; k++)
                mt = fmaxf(mt, SS[r * SPITCH + k]);
            float scale = __expf(mo - mt);
            float lsum = 0.0f;
#pragma unroll 8
            for (int k = 0; k < KTILE; k++) {
                float p = __expf(SS[r * SPITCH + k] - mt);
                SS[r * SPITCH + k] = p;
                lsum += p;
            }
            l_s[r] = l_s[r] * scale + lsum;
            m_s[r] = mt;
            sc_s[r] = scale;
        }
        __syncthreads();

        // rescale accumulator + P @ V   (4 rows x 8 cols per thread)
        float scl[4];
#pragma unroll
        for (int i = 0; i < 4; i++) scl[i] = sc_s[tr * 4 + i];
#pragma unroll
        for (int i = 0; i < 4; i++)
#pragma unroll
            for (int j = 0; j < 8; j++) acco[i][j] *= scl[i];

#pragma unroll 2
        for (int k = 0; k < KTILE; k++) {
            float p[4], v[8];
#pragma unroll
            for (int i = 0; i < 4; i++) p[i] = SS[(tr * 4 + i) * SPITCH + k];
            *(float4*)(v)     = *(float4*)&VS[k * DHD + tc * 8];
            *(float4*)(v + 4) = *(float4*)&VS[k * DHD + tc * 8 + 4];
#pragma unroll
            for (int i = 0; i < 4; i++)
#pragma unroll
                for (int j = 0; j < 8; j++)
                    acco[i][j] += p[i] * v[j];
        }
    }

    // normalize and write to [b, s, h*dh] layout
#pragma unroll
    for (int i = 0; i < 4; i++) {
        int r = tr * 4 + i;
        float rl = 1.0f / l_s[r];
        size_t base = ((size_t)(b * S_LEN + q0 + r)) * D_DIM + h * DHD + tc * 8;
        float4 o1, o2;
        o1.x = acco[i][0] * rl; o1.y = acco[i][1] * rl;
        o1.z = acco[i][2] * rl; o1.w = acco[i][3] * rl;
        o2.x = acco[i][4] * rl; o2.y = acco[i][5] * rl;
        o2.z = acco[i][6] * rl; o2.w = acco[i][7] * rl;
        *(float4*)&g_AO[base]     = o1;
        *(float4*)&g_AO[base + 4] = o2;
    }
}

// ---------------------------------------------------------------------------
// launch
// ---------------------------------------------------------------------------
extern "C" void kernel_launch(void* const* d_in, const int* in_sizes, int n_in,
                              void* d_out, int out_size)
{
    const float* q  = (const float*)d_in[0];
    const float* k  = (const float*)d_in[1];
    const float* v  = (const float*)d_in[2];
    const float* Wq = (const float*)d_in[3];
    const float* bq = (const float*)d_in[4];
    const float* Wk = (const float*)d_in[5];
    const float* bk = (const float*)d_in[6];
    const float* Wv = (const float*)d_in[7];
    const float* bv = (const float*)d_in[8];
    const float* Wo = (const float*)d_in[9];
    const float* bo = (const float*)d_in[10];
    const int* mask = (const int*)d_in[11];
    float* out = (float*)d_out;

    float *pQ, *pK, *pV, *pA;
    cudaGetSymbolAddress((void**)&pQ, g_Q);
    cudaGetSymbolAddress((void**)&pK, g_K);
    cudaGetSymbolAddress((void**)&pV, g_V);
    cudaGetSymbolAddress((void**)&pA, g_AO);

    cudaFuncSetAttribute(flash_attn, cudaFuncAttributeMaxDynamicSharedMemorySize,
                         ATTN_SMEM_BYTES);

    dim3 gg(D_DIM / BN, M_ROWS / BM);  // (16, 32)
    gemm_xwt<<<gg, 256>>>(q, Wq, bq, pQ, M_ROWS, D_DIM, D_DIM);
    gemm_xwt<<<gg, 256>>>(k, Wk, bk, pK, M_ROWS, D_DIM, D_DIM);
    gemm_xwt<<<gg, 256>>>(v, Wv, bv, pV, M_ROWS, D_DIM, D_DIM);

    dim3 ga(S_LEN / QTILE, NH, NB);    // (32, 16, 2)
    flash_attn<<<ga, 256, ATTN_SMEM_BYTES>>>(mask);

    gemm_xwt<<<gg, 256>>>(pA, Wo, bo, out, M_ROWS, D_DIM, D_DIM);
}

// round 3
// speedup vs baseline: 3.0672x; 3.0672x over previous
#include <cuda_runtime.h>
#include <cuda_bf16.h>
#include <cstdint>
#include <math.h>

#define NB 2
#define S_LEN 2048
#define D_DIM 2048
#define NH 16
#define DHD 128
#define M_ROWS 4096
#define KDIM 2048
#define NDIM 2048
#define MK 8388608ull
#define KN 4194304ull
#define MN 8388608ull

// ---------------- scratch (__device__ globals; allocation-guard safe) -------
__device__ float g_QKV[3 * 8388608];            // projected Q,K,V fp32
__device__ float g_AO[8388608];                 // attention out fp32
__device__ __nv_bfloat16 g_INh[3 * 8388608];    // q,k,v hi
__device__ __nv_bfloat16 g_INl[3 * 8388608];    // q,k,v lo
__device__ __nv_bfloat16 g_Wh[4 * 4194304];     // Wq,Wk,Wv,Wo hi
__device__ __nv_bfloat16 g_Wl[4 * 4194304];     // lo
__device__ __nv_bfloat16 g_AOh[8388608];
__device__ __nv_bfloat16 g_AOl[8388608];

// ---------------- PTX helpers (all plain-sm_103-legal) ----------------------
__device__ __forceinline__ uint32_t smem_u32(const void* p) {
    uint32_t a;
    asm("{ .reg .u64 t; cvta.to.shared.u64 t, %1; cvt.u32.u64 %0, t; }"
        : "=r"(a) : "l"(p));
    return a;
}
__device__ __forceinline__ void cp16(uint32_t dst, const void* src) {
    asm volatile("cp.async.cg.shared.global [%0], [%1], 16;\n" :: "r"(dst), "l"(src));
}
__device__ __forceinline__ void cp_commit() {
    asm volatile("cp.async.commit_group;\n" ::: "memory");
}
__device__ __forceinline__ void cp_wait1() {
    asm volatile("cp.async.wait_group 1;\n" ::: "memory");
}
__device__ __forceinline__ void cp_wait0() {
    asm volatile("cp.async.wait_group 0;\n" ::: "memory");
}
__device__ __forceinline__ void ldsm4(uint32_t* r, uint32_t a) {
    asm volatile("ldmatrix.sync.aligned.m8n8.x4.shared.b16 {%0,%1,%2,%3}, [%4];"
                 : "=r"(r[0]), "=r"(r[1]), "=r"(r[2]), "=r"(r[3]) : "r"(a));
}
__device__ __forceinline__ void mma16816(float* c, const uint32_t* a,
                                         const uint32_t* b) {
    asm volatile(
        "mma.sync.aligned.m16n8k16.row.col.f32.bf16.bf16.f32 "
        "{%0,%1,%2,%3}, {%4,%5,%6,%7}, {%8,%9}, {%0,%1,%2,%3};"
        : "+f"(c[0]), "+f"(c[1]), "+f"(c[2]), "+f"(c[3])
        : "r"(a[0]), "r"(a[1]), "r"(a[2]), "r"(a[3]), "r"(b[0]), "r"(b[1]));
}

// ---------------- split conversion fp32 -> (bf16 hi, bf16 lo) --------------
__global__ __launch_bounds__(256) void conv_split(
    const float4* __restrict__ x, __nv_bfloat16* __restrict__ h,
    __nv_bfloat16* __restrict__ l, int n4)
{
    int i = blockIdx.x * blockDim.x + threadIdx.x;
    if (i >= n4) return;
    float4 v = x[i];
    __nv_bfloat16 h0 = __float2bfloat16(v.x);
    __nv_bfloat16 h1 = __float2bfloat16(v.y);
    __nv_bfloat16 h2 = __float2bfloat16(v.z);
    __nv_bfloat16 h3 = __float2bfloat16(v.w);
    __nv_bfloat16 l0 = __float2bfloat16(v.x - __bfloat162float(h0));
    __nv_bfloat16 l1 = __float2bfloat16(v.y - __bfloat162float(h1));
    __nv_bfloat16 l2 = __float2bfloat16(v.z - __bfloat162float(h2));
    __nv_bfloat16 l3 = __float2bfloat16(v.w - __bfloat162float(h3));
    __nv_bfloat162* hp = (__nv_bfloat162*)h;
    __nv_bfloat162* lp = (__nv_bfloat162*)l;
    hp[2 * i]     = __nv_bfloat162{h0, h1};
    hp[2 * i + 1] = __nv_bfloat162{h2, h3};
    lp[2 * i]     = __nv_bfloat162{l0, l1};
    lp[2 * i + 1] = __nv_bfloat162{l2, l3};
}

// ---------------------------------------------------------------------------
// GEMM via mma.sync bf16 3-way split: Y[M,N] = X[M,K] @ W[N,K]^T + bias
// BM=128, BN=128, BK=64, 256 threads (8 warps, 2x4; warp tile 64x32),
// 2-stage cp.async pipeline. XOR-swizzled smem, conflict-free ldmatrix.
// ---------------------------------------------------------------------------
#define GBM 128
#define GBN 128
#define GBK 64
#define GNIT (KDIM / GBK)          // 32
#define STAGE_BYTES 65536          // Ah/Al/Bh/Bl, 16KB each
#define OFF_AL 16384
#define OFF_B  32768
#define GEMM_SMEM (2 * STAGE_BYTES)

__device__ __forceinline__ void g_load_stage(
    uint32_t sbase, int kb,
    const __nv_bfloat16* __restrict__ Xh, const __nv_bfloat16* __restrict__ Xl,
    const __nv_bfloat16* __restrict__ Wh, const __nv_bfloat16* __restrict__ Wl,
    int row0, int col0, int tid)
{
    const int k0 = kb * GBK;
#pragma unroll
    for (int i = 0; i < 8; i++) {            // A: 2048 chunks
        int idx = tid + i * 256;
        int sp = idx >> 10;                  // 0 hi, 1 lo
        int li = idx & 1023;
        int m = li >> 3, g = li & 7;
        const __nv_bfloat16* src =
            (sp ? Xl : Xh) + (size_t)(row0 + m) * KDIM + k0 + g * 8;
        cp16(sbase + sp * 16384 + m * 128 + (((g ^ (m & 7))) << 4), src);
    }
#pragma unroll
    for (int i = 0; i < 8; i++) {            // B: 2048 chunks
        int idx = tid + i * 256;
        int sp = idx >> 10;
        int li = idx & 1023;
        int n = li >> 3, g = li & 7;
        const __nv_bfloat16* src =
            (sp ? Wl : Wh) + (size_t)(col0 + n) * KDIM + k0 + g * 8;
        cp16(sbase + OFF_B + sp * 16384 + n * 128 + (((g ^ (n & 7))) << 4), src);
    }
    cp_commit();
}

__global__ __launch_bounds__(256, 1) void gemm_mma(
    const __nv_bfloat16* __restrict__ XhB, const __nv_bfloat16* __restrict__ XlB,
    const __nv_bfloat16* __restrict__ WhB, const __nv_bfloat16* __restrict__ WlB,
    const float* __restrict__ b0, const float* __restrict__ b1,
    const float* __restrict__ b2, float* __restrict__ YB,
    size_t xzStr, size_t wzStr, size_t yzStr)
{
    extern __shared__ char smraw[];
    const uint32_t tiles = smem_u32(smraw);
    const int tid = threadIdx.x;
    const int z = blockIdx.z;
    const int row0 = blockIdx.y * GBM;
    const int col0 = blockIdx.x * GBN;

    const __nv_bfloat16* Xh = XhB + z * xzStr;
    const __nv_bfloat16* Xl = XlB + z * xzStr;
    const __nv_bfloat16* Wh = WhB + z * wzStr;
    const __nv_bfloat16* Wl = WlB + z * wzStr;
    const float* bias = (z == 0) ? b0 : ((z == 1) ? b1 : b2);
    float* Y = YB + z * yzStr;

    const int lane = tid & 31;
    const int q = lane >> 3, lr = lane & 7;
    const int wm = (tid >> 5) >> 2;      // 0..1
    const int wn = (tid >> 5) & 3;       // 0..3
    const int aKh = q >> 1;              // A k-half selector
    const int bKh = q & 1;               // B k-half selector

    int mA[4], nBr[2];
#pragma unroll
    for (int mb = 0; mb < 4; mb++) mA[mb] = wm * 64 + mb * 16 + ((q & 1) << 3) + lr;
#pragma unroll
    for (int nb = 0; nb < 2; nb++) nBr[nb] = wn * 32 + nb * 16 + ((q >> 1) << 3) + lr;

    float acc[4][4][4];
#pragma unroll
    for (int a = 0; a < 4; a++)
#pragma unroll
        for (int b = 0; b < 4; b++)
#pragma unroll
            for (int c = 0; c < 4; c++) acc[a][b][c] = 0.0f;

    g_load_stage(tiles, 0, Xh, Xl, Wh, Wl, row0, col0, tid);

    for (int it = 0; it < GNIT; it++) {
        const uint32_t sbase = tiles + (it & 1) * STAGE_BYTES;
        if (it + 1 < GNIT) {
            g_load_stage(tiles + ((it + 1) & 1) * STAGE_BYTES, it + 1,
                         Xh, Xl, Wh, Wl, row0, col0, tid);
            cp_wait1();
        } else {
            cp_wait0();
        }
        __syncthreads();

#pragma unroll
        for (int kk = 0; kk < 4; kk++) {
            uint32_t a_h[4][4], a_l[4][4], b_h[2][4], b_l[2][4];
#pragma unroll
            for (int mb = 0; mb < 4; mb++) {
                uint32_t ad = sbase + mA[mb] * 128 +
                              ((uint32_t)((kk * 2 + aKh) ^ (mA[mb] & 7)) << 4);
                ldsm4(a_h[mb], ad);
                ldsm4(a_l[mb], ad + OFF_AL);
            }
#pragma unroll
            for (int nb = 0; nb < 2; nb++) {
                uint32_t bd = sbase + OFF_B + nBr[nb] * 128 +
                              ((uint32_t)((kk * 2 + bKh) ^ (nBr[nb] & 7)) << 4);
                ldsm4(b_h[nb], bd);
                ldsm4(b_l[nb], bd + 16384);
            }
#pragma unroll
            for (int mb = 0; mb < 4; mb++)
#pragma unroll
                for (int nb = 0; nb < 2; nb++) {
                    mma16816(acc[mb][2 * nb],     a_h[mb], b_h[nb]);
                    mma16816(acc[mb][2 * nb + 1], a_h[mb], b_h[nb] + 2);
                    mma16816(acc[mb][2 * nb],     a_l[mb], b_h[nb]);
                    mma16816(acc[mb][2 * nb + 1], a_l[mb], b_h[nb] + 2);
                    mma16816(acc[mb][2 * nb],     a_h[mb], b_l[nb]);
                    mma16816(acc[mb][2 * nb + 1], a_h[mb], b_l[nb] + 2);
                }
        }
        __syncthreads();
    }

    // epilogue
#pragma unroll
    for (int mb = 0; mb < 4; mb++) {
        int gr = row0 + wm * 64 + mb * 16 + (lane >> 2);
#pragma unroll
        for (int n8 = 0; n8 < 4; n8++) {
            int gc = col0 + wn * 32 + n8 * 8 + ((lane & 3) << 1);
            float bx = bias[gc], by = bias[gc + 1];
            float* c = acc[mb][n8];
            float2 o0 = {c[0] + bx, c[1] + by};
            float2 o1 = {c[2] + bx, c[3] + by};
            *(float2*)&Y[(size_t)gr * NDIM + gc] = o0;
            *(float2*)&Y[(size_t)(gr + 8) * NDIM + gc] = o1;
        }
    }
}

// ---------------------------------------------------------------------------
// Flash attention (causal), fp32, shuffle-parallel online softmax.
// One block = 64-query tile for one (b,h).
// ---------------------------------------------------------------------------
#define QTILE 64
#define KTILE 64
#define SPITCH 65

__device__ __forceinline__ int swz(int d, int cg) {
    return d * 64 + (((cg) ^ (d & 15)) << 2);
}

#define ATTN_SMEM_FLOATS (8192 + 8192 + 8192 + 64 * SPITCH)
#define ATTN_SMEM_BYTES (ATTN_SMEM_FLOATS * 4)

__global__ __launch_bounds__(256) void flash_attn(const int* __restrict__ maskp)
{
    extern __shared__ float sm[];
    float* QT = sm;
    float* KT = QT + 8192;
    float* VS = KT + 8192;
    float* SS = VS + 8192;

    const int tid = threadIdx.x;
    const int tr = tid >> 4;
    const int tc = tid & 15;
    const int qt = blockIdx.x;
    const int h  = blockIdx.y;
    const int b  = blockIdx.z;
    const int q0 = qt * QTILE;

    const float* Qg = g_QKV + 0 * MK + (size_t)b * S_LEN * D_DIM + h * DHD;
    const float* Kg = g_QKV + 1 * MK + (size_t)b * S_LEN * D_DIM + h * DHD;
    const float* Vg = g_QKV + 2 * MK + (size_t)b * S_LEN * D_DIM + h * DHD;

    for (int f = tid; f < QTILE * DHD; f += 256) {
        int r = f >> 7, d = f & 127;
        QT[swz(d, r >> 2) + (r & 3)] = Qg[(size_t)(q0 + r) * D_DIM + d];
    }

    float acco[4][8];
    float m_old[4], l_run[4];
#pragma unroll
    for (int i = 0; i < 4; i++) {
        m_old[i] = -1e30f;
        l_run[i] = 0.0f;
#pragma unroll
        for (int j = 0; j < 8; j++) acco[i][j] = 0.0f;
    }

    const int causal = maskp[0];
    const int ktmax = causal ? qt : (S_LEN / KTILE - 1);
    const float isq = 0.08838834764831845f;   // 1/sqrt(128)

    for (int kt = 0; kt <= ktmax; kt++) {
        const int k0 = kt * KTILE;
        __syncthreads();   // protect KT/VS/SS from previous-iter readers

        for (int f = tid; f < KTILE * DHD; f += 256) {
            int r = f >> 7, d = f & 127;
            KT[swz(d, r >> 2) + (r & 3)] = Kg[(size_t)(k0 + r) * D_DIM + d];
        }
        for (int f = tid; f < KTILE * (DHD / 4); f += 256) {
            int r = f >> 5, d4 = (f & 31) << 2;
            *(float4*)&VS[r * DHD + d4] =
                *(const float4*)&Vg[(size_t)(k0 + r) * D_DIM + d4];
        }
        __syncthreads();

        // S = Q K^T (4x4 per thread)
        float accs[4][4];
#pragma unroll
        for (int i = 0; i < 4; i++)
#pragma unroll
            for (int j = 0; j < 4; j++) accs[i][j] = 0.0f;

#pragma unroll 4
        for (int d = 0; d < DHD; d++) {
            float aq[4], bk[4];
            *(float4*)aq = *(float4*)&QT[swz(d, tr)];
            *(float4*)bk = *(float4*)&KT[swz(d, tc)];
#pragma unroll
            for (int i = 0; i < 4; i++)
#pragma unroll
                for (int j = 0; j < 4; j++)
                    accs[i][j] += aq[i] * bk[j];
        }

        // scale + causal mask
#pragma unroll
        for (int i = 0; i < 4; i++) {
            int gq = q0 + tr * 4 + i;
#pragma unroll
            for (int j = 0; j < 4; j++) {
                int gk = k0 + tc * 4 + j;
                float s = accs[i][j] * isq;
                if (causal && gk > gq) s = -1e30f;
                accs[i][j] = s;
            }
        }

        // online softmax: row reductions via shfl across the 16 tc lanes
#pragma unroll
        for (int i = 0; i < 4; i++) {
            float rm = fmaxf(fmaxf(accs[i][0], accs[i][1]),
                             fmaxf(accs[i][2], accs[i][3]));
#pragma unroll
            for (int d = 1; d < 16; d <<= 1)
                rm = fmaxf(rm, __shfl_xor_sync(0xffffffffu, rm, d));
            float mn = fmaxf(m_old[i], rm);
            float sc = __expf(m_old[i] - mn);
            m_old[i] = mn;
            float rs = 0.0f;
#pragma unroll
            for (int j = 0; j < 4; j++) {
                float p = __expf(accs[i][j] - mn);
                accs[i][j] = p;
                rs += p;
            }
#pragma unroll
            for (int d = 1; d < 16; d <<= 1)
                rs += __shfl_xor_sync(0xffffffffu, rs, d);
            l_run[i] = l_run[i] * sc + rs;
#pragma unroll
            for (int j = 0; j < 8; j++) acco[i][j] *= sc;
            // store P row chunk
#pragma unroll
            for (int j = 0; j < 4; j++)
                SS[(tr * 4 + i) * SPITCH + tc * 4 + j] = accs[i][j];
        }
        __syncthreads();

        // P @ V (4 rows x 8 cols per thread)
#pragma unroll 2
        for (int k = 0; k < KTILE; k++) {
            float p[4], v[8];
#pragma unroll
            for (int i = 0; i < 4; i++) p[i] = SS[(tr * 4 + i) * SPITCH + k];
            *(float4*)(v)     = *(float4*)&VS[k * DHD + tc * 8];
            *(float4*)(v + 4) = *(float4*)&VS[k * DHD + tc * 8 + 4];
#pragma unroll
            for (int i = 0; i < 4; i++)
#pragma unroll
                for (int j = 0; j < 8; j++)
                    acco[i][j] += p[i] * v[j];
        }
    }

    // normalize and write [b, s, h*dh]
#pragma unroll
    for (int i = 0; i < 4; i++) {
        int r = tr * 4 + i;
        float rl = 1.0f / l_run[i];
        size_t base = ((size_t)(b * S_LEN + q0 + r)) * D_DIM + h * DHD + tc * 8;
        float4 o1, o2;
        o1.x = acco[i][0] * rl; o1.y = acco[i][1] * rl;
        o1.z = acco[i][2] * rl; o1.w = acco[i][3] * rl;
        o2.x = acco[i][4] * rl; o2.y = acco[i][5] * rl;
        o2.z = acco[i][6] * rl; o2.w = acco[i][7] * rl;
        *(float4*)&g_AO[base]     = o1;
        *(float4*)&g_AO[base + 4] = o2;
    }
}

// ---------------------------------------------------------------------------
extern "C" void kernel_launch(void* const* d_in, const int* in_sizes, int n_in,
                              void* d_out, int out_size)
{
    const float* q  = (const float*)d_in[0];
    const float* k  = (const float*)d_in[1];
    const float* v  = (const float*)d_in[2];
    const float* Wq = (const float*)d_in[3];
    const float* bq = (const float*)d_in[4];
    const float* Wk = (const float*)d_in[5];
    const float* bk = (const float*)d_in[6];
    const float* Wv = (const float*)d_in[7];
    const float* bv = (const float*)d_in[8];
    const float* Wo = (const float*)d_in[9];
    const float* bo = (const float*)d_in[10];
    const int* mask = (const int*)d_in[11];
    float* out = (float*)d_out;

    float *pQKV, *pAO;
    __nv_bfloat16 *pINh, *pINl, *pWh, *pWl, *pAOh, *pAOl;
    cudaGetSymbolAddress((void**)&pQKV, g_QKV);
    cudaGetSymbolAddress((void**)&pAO,  g_AO);
    cudaGetSymbolAddress((void**)&pINh, g_INh);
    cudaGetSymbolAddress((void**)&pINl, g_INl);
    cudaGetSymbolAddress((void**)&pWh,  g_Wh);
    cudaGetSymbolAddress((void**)&pWl,  g_Wl);
    cudaGetSymbolAddress((void**)&pAOh, g_AOh);
    cudaGetSymbolAddress((void**)&pAOl, g_AOl);

    cudaFuncSetAttribute(flash_attn, cudaFuncAttributeMaxDynamicSharedMemorySize,
                         ATTN_SMEM_BYTES);
    cudaFuncSetAttribute(gemm_mma, cudaFuncAttributeMaxDynamicSharedMemorySize,
                         GEMM_SMEM);

    // split-convert inputs and weights
    conv_split<<<8192, 256>>>((const float4*)q, pINh + 0 * MK, pINl + 0 * MK, MK / 4);
    conv_split<<<8192, 256>>>((const float4*)k, pINh + 1 * MK, pINl + 1 * MK, MK / 4);
    conv_split<<<8192, 256>>>((const float4*)v, pINh + 2 * MK, pINl + 2 * MK, MK / 4);
    conv_split<<<4096, 256>>>((const float4*)Wq, pWh + 0 * KN, pWl + 0 * KN, KN / 4);
    conv_split<<<4096, 256>>>((const float4*)Wk, pWh + 1 * KN, pWl + 1 * KN, KN / 4);
    conv_split<<<4096, 256>>>((const float4*)Wv, pWh + 2 * KN, pWl + 2 * KN, KN / 4);
    conv_split<<<4096, 256>>>((const float4*)Wo, pWh + 3 * KN, pWl + 3 * KN, KN / 4);

    // fused Q/K/V projections (tensor cores, 3-way split)
    dim3 gqkv(NDIM / GBN, M_ROWS / GBM, 3);   // (16, 32, 3)
    gemm_mma<<<gqkv, 256, GEMM_SMEM>>>(pINh, pINl, pWh, pWl, bq, bk, bv,
                                       pQKV, MK, KN, MN);

    // attention
    dim3 ga(S_LEN / QTILE, NH, NB);           // (32, 16, 2)
    flash_attn<<<ga, 256, ATTN_SMEM_BYTES>>>(mask);

    // O projection
    conv_split<<<8192, 256>>>((const float4*)pAO, pAOh, pAOl, MK / 4);
    dim3 go(NDIM / GBN, M_ROWS / GBM, 1);
    gemm_mma<<<go, 256, GEMM_SMEM>>>(pAOh, pAOl, pWh + 3 * KN, pWl + 3 * KN,
                                     bo, bo, bo, out, 0, 0, 0);
}

// round 5
// speedup vs baseline: 5.6314x; 1.8360x over previous
#include <cuda_runtime.h>
#include <cuda_bf16.h>
#include <cstdint>
#include <math.h>

#define NB 2
#define S_LEN 2048
#define D_DIM 2048
#define NH 16
#define DHD 128
#define M_ROWS 4096
#define KDIM 2048
#define NDIM 2048
#define MK 8388608ull
#define KN 4194304ull

// ---------------- scratch (__device__ globals; allocation-guard safe) -------
__device__ __nv_bfloat16 g_INh[3 * 8388608];    // q,k,v inputs hi
__device__ __nv_bfloat16 g_INl[3 * 8388608];    // lo
__device__ __nv_bfloat16 g_Wh[4 * 4194304];     // Wq,Wk,Wv,Wo hi
__device__ __nv_bfloat16 g_Wl[4 * 4194304];     // lo
__device__ __nv_bfloat16 g_Ph[3 * 8388608];     // projected Q,K,V hi
__device__ __nv_bfloat16 g_Pl[3 * 8388608];     // lo
__device__ __nv_bfloat16 g_VTh[8388608];        // V transposed [b, D, s] hi
__device__ __nv_bfloat16 g_VTl[8388608];        // lo
__device__ __nv_bfloat16 g_AOh[8388608];        // attention out hi
__device__ __nv_bfloat16 g_AOl[8388608];        // lo

// ---------------- PTX helpers (plain-sm_103-legal) --------------------------
__device__ __forceinline__ uint32_t smem_u32(const void* p) {
    uint32_t a;
    asm("{ .reg .u64 t; cvta.to.shared.u64 t, %1; cvt.u32.u64 %0, t; }"
        : "=r"(a) : "l"(p));
    return a;
}
__device__ __forceinline__ void cp16(uint32_t dst, const void* src) {
    asm volatile("cp.async.cg.shared.global [%0], [%1], 16;\n" :: "r"(dst), "l"(src));
}
__device__ __forceinline__ void cp_commit() {
    asm volatile("cp.async.commit_group;\n" ::: "memory");
}
__device__ __forceinline__ void cp_wait1() {
    asm volatile("cp.async.wait_group 1;\n" ::: "memory");
}
__device__ __forceinline__ void cp_wait0() {
    asm volatile("cp.async.wait_group 0;\n" ::: "memory");
}
__device__ __forceinline__ void ldsm4(uint32_t* r, uint32_t a) {
    asm volatile("ldmatrix.sync.aligned.m8n8.x4.shared.b16 {%0,%1,%2,%3}, [%4];"
                 : "=r"(r[0]), "=r"(r[1]), "=r"(r[2]), "=r"(r[3]) : "r"(a));
}
__device__ __forceinline__ void mma16816(float* c, const uint32_t* a,
                                         const uint32_t* b) {
    asm volatile(
        "mma.sync.aligned.m16n8k16.row.col.f32.bf16.bf16.f32 "
        "{%0,%1,%2,%3}, {%4,%5,%6,%7}, {%8,%9}, {%0,%1,%2,%3};"
        : "+f"(c[0]), "+f"(c[1]), "+f"(c[2]), "+f"(c[3])
        : "r"(a[0]), "r"(a[1]), "r"(a[2]), "r"(a[3]), "r"(b[0]), "r"(b[1]));
}
__device__ __forceinline__ uint32_t pack_bf16(float lo, float hi) {
    uint32_t d;
    asm("cvt.rn.bf16x2.f32 %0, %1, %2;" : "=r"(d) : "f"(hi), "f"(lo));
    return d;
}
__device__ __forceinline__ float ex2f(float x) {
    float y;
    asm("ex2.approx.f32 %0, %1;" : "=f"(y) : "f"(x));
    return y;
}

// ---------------- split conversion fp32 -> (bf16 hi, bf16 lo) --------------
__global__ __launch_bounds__(256) void conv_split(
    const float4* __restrict__ x, __nv_bfloat16* __restrict__ h,
    __nv_bfloat16* __restrict__ l, int n4)
{
    int i = blockIdx.x * blockDim.x + threadIdx.x;
    if (i >= n4) return;
    float4 v = x[i];
    uint32_t hp0 = pack_bf16(v.x, v.y);
    uint32_t hp1 = pack_bf16(v.z, v.w);
    float h0 = __uint_as_float(hp0 << 16), h1 = __uint_as_float(hp0 & 0xffff0000u);
    float h2 = __uint_as_float(hp1 << 16), h3 = __uint_as_float(hp1 & 0xffff0000u);
    uint32_t lp0 = pack_bf16(v.x - h0, v.y - h1);
    uint32_t lp1 = pack_bf16(v.z - h2, v.w - h3);
    uint32_t* hp = (uint32_t*)h;
    uint32_t* lp = (uint32_t*)l;
    hp[2 * i] = hp0; hp[2 * i + 1] = hp1;
    lp[2 * i] = lp0; lp[2 * i + 1] = lp1;
}

// ---------------- V transpose: [b, s, D] -> [b, D, s] (bf16 hi+lo) ----------
__global__ __launch_bounds__(256) void transpose_v(
    const __nv_bfloat16* __restrict__ inh, const __nv_bfloat16* __restrict__ inl,
    __nv_bfloat16* __restrict__ outh, __nv_bfloat16* __restrict__ outl)
{
    __shared__ __nv_bfloat16 th[32][33];
    __shared__ __nv_bfloat16 tl[32][33];
    const int tx = threadIdx.x, ty = threadIdx.y;
    const int s0 = blockIdx.x * 32, D0 = blockIdx.y * 32;
    const size_t bb = (size_t)blockIdx.z * 2048 * 2048;
#pragma unroll
    for (int k = 0; k < 4; k++) {
        int s = s0 + ty + k * 8;
        th[ty + k * 8][tx] = inh[bb + (size_t)s * 2048 + D0 + tx];
        tl[ty + k * 8][tx] = inl[bb + (size_t)s * 2048 + D0 + tx];
    }
    __syncthreads();
#pragma unroll
    for (int k = 0; k < 4; k++) {
        int D = D0 + ty + k * 8;
        outh[bb + (size_t)D * 2048 + s0 + tx] = th[tx][ty + k * 8];
        outl[bb + (size_t)D * 2048 + s0 + tx] = tl[tx][ty + k * 8];
    }
}

// ---------------------------------------------------------------------------
// GEMM via mma.sync bf16 3-way split: Y = X @ W^T + bias
// Writes fp32 (Y) or bf16 hi/lo (Yh/Yl) depending on Yh != nullptr.
// ---------------------------------------------------------------------------
#define GBM 128
#define GBN 128
#define GBK 64
#define GNIT (KDIM / GBK)
#define STAGE_BYTES 65536
#define OFF_AL 16384
#define OFF_B  32768
#define GEMM_SMEM (2 * STAGE_BYTES)

__device__ __forceinline__ void g_load_stage(
    uint32_t sbase, int kb,
    const __nv_bfloat16* __restrict__ Xh, const __nv_bfloat16* __restrict__ Xl,
    const __nv_bfloat16* __restrict__ Wh, const __nv_bfloat16* __restrict__ Wl,
    int row0, int col0, int tid)
{
    const int k0 = kb * GBK;
#pragma unroll
    for (int i = 0; i < 8; i++) {
        int idx = tid + i * 256;
        int sp = idx >> 10;
        int li = idx & 1023;
        int m = li >> 3, g = li & 7;
        const __nv_bfloat16* src =
            (sp ? Xl : Xh) + (size_t)(row0 + m) * KDIM + k0 + g * 8;
        cp16(sbase + sp * 16384 + m * 128 + (((g ^ (m & 7))) << 4), src);
    }
#pragma unroll
    for (int i = 0; i < 8; i++) {
        int idx = tid + i * 256;
        int sp = idx >> 10;
        int li = idx & 1023;
        int n = li >> 3, g = li & 7;
        const __nv_bfloat16* src =
            (sp ? Wl : Wh) + (size_t)(col0 + n) * KDIM + k0 + g * 8;
        cp16(sbase + OFF_B + sp * 16384 + n * 128 + (((g ^ (n & 7))) << 4), src);
    }
    cp_commit();
}

__global__ __launch_bounds__(256, 1) void gemm_mma(
    const __nv_bfloat16* __restrict__ XhB, const __nv_bfloat16* __restrict__ XlB,
    const __nv_bfloat16* __restrict__ WhB, const __nv_bfloat16* __restrict__ WlB,
    const float* __restrict__ b0, const float* __restrict__ b1,
    const float* __restrict__ b2, float* __restrict__ Y,
    __nv_bfloat16* __restrict__ YhB, __nv_bfloat16* __restrict__ YlB,
    size_t xzStr, size_t wzStr)
{
    extern __shared__ char smraw[];
    const uint32_t tiles = smem_u32(smraw);
    const int tid = threadIdx.x;
    const int z = blockIdx.z;
    const int row0 = blockIdx.y * GBM;
    const int col0 = blockIdx.x * GBN;

    const __nv_bfloat16* Xh = XhB + z * xzStr;
    const __nv_bfloat16* Xl = XlB + z * xzStr;
    const __nv_bfloat16* Wh = WhB + z * wzStr;
    const __nv_bfloat16* Wl = WlB + z * wzStr;
    const float* bias = (z == 0) ? b0 : ((z == 1) ? b1 : b2);

    const int lane = tid & 31;
    const int q = lane >> 3, lr = lane & 7;
    const int wm = (tid >> 5) >> 2;
    const int wn = (tid >> 5) & 3;
    const int aKh = q >> 1;
    const int bKh = q & 1;

    int mA[4], nBr[2];
#pragma unroll
    for (int mb = 0; mb < 4; mb++) mA[mb] = wm * 64 + mb * 16 + ((q & 1) << 3) + lr;
#pragma unroll
    for (int nb = 0; nb < 2; nb++) nBr[nb] = wn * 32 + nb * 16 + ((q >> 1) << 3) + lr;

    float acc[4][4][4];
#pragma unroll
    for (int a = 0; a < 4; a++)
#pragma unroll
        for (int b = 0; b < 4; b++)
#pragma unroll
            for (int c = 0; c < 4; c++) acc[a][b][c] = 0.0f;

    g_load_stage(tiles, 0, Xh, Xl, Wh, Wl, row0, col0, tid);

    for (int it = 0; it < GNIT; it++) {
        const uint32_t sbase = tiles + (it & 1) * STAGE_BYTES;
        if (it + 1 < GNIT) {
            g_load_stage(tiles + ((it + 1) & 1) * STAGE_BYTES, it + 1,
                         Xh, Xl, Wh, Wl, row0, col0, tid);
            cp_wait1();
        } else {
            cp_wait0();
        }
        __syncthreads();

#pragma unroll
        for (int kk = 0; kk < 4; kk++) {
            uint32_t a_h[4][4], a_l[4][4], b_h[2][4], b_l[2][4];
#pragma unroll
            for (int mb = 0; mb < 4; mb++) {
                uint32_t ad = sbase + mA[mb] * 128 +
                              ((uint32_t)((kk * 2 + aKh) ^ (mA[mb] & 7)) << 4);
                ldsm4(a_h[mb], ad);
                ldsm4(a_l[mb], ad + OFF_AL);
            }
#pragma unroll
            for (int nb = 0; nb < 2; nb++) {
                uint32_t bd = sbase + OFF_B + nBr[nb] * 128 +
                              ((uint32_t)((kk * 2 + bKh) ^ (nBr[nb] & 7)) << 4);
                ldsm4(b_h[nb], bd);
                ldsm4(b_l[nb], bd + 16384);
            }
#pragma unroll
            for (int mb = 0; mb < 4; mb++)
#pragma unroll
                for (int nb = 0; nb < 2; nb++) {
                    mma16816(acc[mb][2 * nb],     a_h[mb], b_h[nb]);
                    mma16816(acc[mb][2 * nb + 1], a_h[mb], b_h[nb] + 2);
                    mma16816(acc[mb][2 * nb],     a_l[mb], b_h[nb]);
                    mma16816(acc[mb][2 * nb + 1], a_l[mb], b_h[nb] + 2);
                    mma16816(acc[mb][2 * nb],     a_h[mb], b_l[nb]);
                    mma16816(acc[mb][2 * nb + 1], a_h[mb], b_l[nb] + 2);
                }
        }
        __syncthreads();
    }

    // epilogue
    if (YhB) {
        __nv_bfloat16* Yh = YhB + z * MK;
        __nv_bfloat16* Yl = YlB + z * MK;
#pragma unroll
        for (int mb = 0; mb < 4; mb++) {
            int gr = row0 + wm * 64 + mb * 16 + (lane >> 2);
#pragma unroll
            for (int n8 = 0; n8 < 4; n8++) {
                int gc = col0 + wn * 32 + n8 * 8 + ((lane & 3) << 1);
                float bx = bias[gc], by = bias[gc + 1];
                float* c = acc[mb][n8];
#pragma unroll
                for (int rr = 0; rr < 2; rr++) {
                    float v0 = c[2 * rr] + bx, v1 = c[2 * rr + 1] + by;
                    uint32_t hp = pack_bf16(v0, v1);
                    float h0 = __uint_as_float(hp << 16);
                    float h1 = __uint_as_float(hp & 0xffff0000u);
                    uint32_t lp = pack_bf16(v0 - h0, v1 - h1);
                    size_t pidx = ((size_t)(gr + rr * 8) * NDIM + gc) >> 1;
                    ((uint32_t*)Yh)[pidx] = hp;
                    ((uint32_t*)Yl)[pidx] = lp;
                }
            }
        }
    } else {
#pragma unroll
        for (int mb = 0; mb < 4; mb++) {
            int gr = row0 + wm * 64 + mb * 16 + (lane >> 2);
#pragma unroll
            for (int n8 = 0; n8 < 4; n8++) {
                int gc = col0 + wn * 32 + n8 * 8 + ((lane & 3) << 1);
                float bx = bias[gc], by = bias[gc + 1];
                float* c = acc[mb][n8];
                float2 o0 = {c[0] + bx, c[1] + by};
                float2 o1 = {c[2] + bx, c[3] + by};
                *(float2*)&Y[(size_t)gr * NDIM + gc] = o0;
                *(float2*)&Y[(size_t)(gr + 8) * NDIM + gc] = o1;
            }
        }
    }
}

// ---------------------------------------------------------------------------
// Flash attention on mma.sync, 3-way split, online softmax in fragments.
// CTA: 128 q-rows x (b,h). 8 warps, each 16 q-rows. KV tile = 64.
// smem: stage{K hi/lo 32KB + VT hi/lo 32KB} x2 + Q hi/lo 64KB = 192KB
// ---------------------------------------------------------------------------
#define FA_STAGE 65536
#define FA_QOFF  131072
#define FA_SMEM  196608

__device__ __forceinline__ void fa_load_q(
    uint32_t qb, const __nv_bfloat16* Qh, const __nv_bfloat16* Ql,
    size_t rowbase, int tid)
{
#pragma unroll
    for (int i = 0; i < 16; i++) {
        int idx = tid + i * 256;
        int sp = idx >> 11;
        int li = idx & 2047;
        int m = li >> 4, g = li & 15;
        const __nv_bfloat16* src = (sp ? Ql : Qh) + (rowbase + m) * 2048 + g * 8;
        cp16(qb + sp * 32768 + (g >> 3) * 16384 + m * 128 +
             ((uint32_t)((g & 7) ^ (m & 7)) << 4), src);
    }
}

__device__ __forceinline__ void fa_load_kv(
    uint32_t sb, const __nv_bfloat16* Kh, const __nv_bfloat16* Kl,
    const __nv_bfloat16* VTh, const __nv_bfloat16* VTl,
    size_t krowbase, size_t vrowbase, int k0, int tid)
{
#pragma unroll
    for (int i = 0; i < 8; i++) {
        int idx = tid + i * 256;
        int sp = idx >> 10;
        int li = idx & 1023;
        int n = li >> 4, g = li & 15;
        const __nv_bfloat16* src = (sp ? Kl : Kh) + (krowbase + k0 + n) * 2048 + g * 8;
        cp16(sb + sp * 16384 + (g >> 3) * 8192 + n * 128 +
             ((uint32_t)((g & 7) ^ (n & 7)) << 4), src);
    }
#pragma unroll
    for (int i = 0; i < 8; i++) {
        int idx = tid + i * 256;
        int sp = idx >> 10;
        int li = idx & 1023;
        int d = li >> 3, g = li & 7;
        const __nv_bfloat16* src = (sp ? VTl : VTh) + (vrowbase + d) * 2048 + k0 + g * 8;
        cp16(sb + 32768 + sp * 16384 + d * 128 +
             ((uint32_t)(g ^ (d & 7)) << 4), src);
    }
    cp_commit();
}

__global__ __launch_bounds__(256, 1) void flash_attn(const int* __restrict__ maskp)
{
    extern __shared__ char smraw[];
    const uint32_t tiles = smem_u32(smraw);
    const uint32_t qb = tiles + FA_QOFF;
    const int tid = threadIdx.x;
    const int lane = tid & 31;
    const int q = lane >> 3, lr = lane & 7;
    const int wm = tid >> 5;                 // warp 0..7, rows wm*16..+15
    const int qt = (int)gridDim.x - 1 - (int)blockIdx.x;   // heavy blocks first
    const int h = blockIdx.y;
    const int b = blockIdx.z;
    const int q0 = qt * 128;

    const size_t qrowbase = ((size_t)b * 2048 + q0) * 1 /*rows*/;
    // element bases (row index units); column offset h*128 folded into row*2048 math
    const size_t qbase = (size_t)b * 2048 + q0;       // + m rows; col h*128
    const size_t krowb = (size_t)b * 2048;            // + k rows
    const size_t vrowb = (size_t)b * 2048 + h * 128;  // + d rows (VT layout)

    const __nv_bfloat16* Qh = g_Ph + 0 * MK + h * 128;
    const __nv_bfloat16* Ql = g_Pl + 0 * MK + h * 128;
    const __nv_bfloat16* Kh = g_Ph + 1 * MK + h * 128;
    const __nv_bfloat16* Kl = g_Pl + 1 * MK + h * 128;

    const int causal = maskp[0];
    const int ktmax = causal ? (2 * qt + 1) : (S_LEN / 64 - 1);

    float acc_o[16][4];
#pragma unroll
    for (int i = 0; i < 16; i++)
#pragma unroll
        for (int j = 0; j < 4; j++) acc_o[i][j] = 0.0f;
    float m2[2] = {-1e30f, -1e30f};
    float lsum[2] = {0.0f, 0.0f};

    const float Cs = 0.08838834764831845f * 1.4426950408889634f;  // isq*log2e

    fa_load_q(qb, Qh, Ql, qbase, tid);
    fa_load_kv(tiles, Kh, Kl, g_VTh, g_VTl, krowb, vrowb, 0, tid);

    for (int kt = 0; kt <= ktmax; kt++) {
        const uint32_t sb = tiles + (kt & 1) * FA_STAGE;
        const int k0 = kt * 64;
        if (kt + 1 <= ktmax) {
            fa_load_kv(tiles + ((kt + 1) & 1) * FA_STAGE, Kh, Kl, g_VTh, g_VTl,
                       krowb, vrowb, (kt + 1) * 64, tid);
            cp_wait1();
        } else {
            cp_wait0();
        }
        __syncthreads();

        // ---- S = Q K^T : warp tile 16 x 64 ----
        float s[8][4];
#pragma unroll
        for (int nb = 0; nb < 8; nb++)
#pragma unroll
            for (int e = 0; e < 4; e++) s[nb][e] = 0.0f;

        const int arow = wm * 16 + ((q & 1) << 3) + lr;
        const int aKh = q >> 1;
        const int brow_base = ((q >> 1) << 3) + lr;
        const int bKh = q & 1;

#pragma unroll
        for (int kc = 0; kc < 8; kc++) {
            uint32_t ah[4], al[4];
            uint32_t aad = qb + (kc >> 2) * 16384 + arow * 128 +
                           ((uint32_t)(((kc & 3) * 2 + aKh) ^ (arow & 7)) << 4);
            ldsm4(ah, aad);
            ldsm4(al, aad + 32768);
#pragma unroll
            for (int nb2 = 0; nb2 < 4; nb2++) {
                int nrow = nb2 * 16 + brow_base;
                uint32_t bad = sb + (kc >> 2) * 8192 + nrow * 128 +
                               ((uint32_t)(((kc & 3) * 2 + bKh) ^ (nrow & 7)) << 4);
                uint32_t bh[4], bl[4];
                ldsm4(bh, bad);
                ldsm4(bl, bad + 16384);
                mma16816(s[2 * nb2],     ah, bh);
                mma16816(s[2 * nb2 + 1], ah, bh + 2);
                mma16816(s[2 * nb2],     al, bh);
                mma16816(s[2 * nb2 + 1], al, bh + 2);
                mma16816(s[2 * nb2],     ah, bl);
                mma16816(s[2 * nb2 + 1], ah, bl + 2);
            }
        }

        // ---- softmax in fragments ----
        const int masked = causal && (kt >= 2 * qt);
        const int r0 = lane >> 2;
        const int c0 = (lane & 3) << 1;
#pragma unroll
        for (int nb = 0; nb < 8; nb++) {
#pragma unroll
            for (int e = 0; e < 4; e++) {
                float t = s[nb][e] * Cs;
                if (masked) {
                    int gq = q0 + wm * 16 + r0 + (e >> 1) * 8;
                    int gk = k0 + nb * 8 + c0 + (e & 1);
                    if (gk > gq) t = -1e30f;
                }
                s[nb][e] = t;
            }
        }
#pragma unroll
        for (int r2 = 0; r2 < 2; r2++) {
            float rm = -1e30f;
#pragma unroll
            for (int nb = 0; nb < 8; nb++)
                rm = fmaxf(rm, fmaxf(s[nb][2 * r2], s[nb][2 * r2 + 1]));
            rm = fmaxf(rm, __shfl_xor_sync(0xffffffffu, rm, 1));
            rm = fmaxf(rm, __shfl_xor_sync(0xffffffffu, rm, 2));
            float mn = fmaxf(m2[r2], rm);
            float sc = ex2f(m2[r2] - mn);
            m2[r2] = mn;
            float rs = 0.0f;
#pragma unroll
            for (int nb = 0; nb < 8; nb++) {
                float p0 = ex2f(s[nb][2 * r2] - mn);
                float p1 = ex2f(s[nb][2 * r2 + 1] - mn);
                s[nb][2 * r2] = p0;
                s[nb][2 * r2 + 1] = p1;
                rs += p0 + p1;
            }
            rs += __shfl_xor_sync(0xffffffffu, rs, 1);
            rs += __shfl_xor_sync(0xffffffffu, rs, 2);
            lsum[r2] = lsum[r2] * sc + rs;
#pragma unroll
            for (int nb = 0; nb < 16; nb++) {
                acc_o[nb][2 * r2] *= sc;
                acc_o[nb][2 * r2 + 1] *= sc;
            }
        }

        // ---- O += P V : P frags from s, V from smem (VT) ----
#pragma unroll
        for (int kc2 = 0; kc2 < 4; kc2++) {
            uint32_t ph[4], pl[4];
#pragma unroll
            for (int half = 0; half < 2; half++) {     // s blocks 2kc2, 2kc2+1
                float* sp0 = s[2 * kc2 + half];
                uint32_t h0 = pack_bf16(sp0[0], sp0[1]);
                uint32_t h1 = pack_bf16(sp0[2], sp0[3]);
                ph[2 * half] = h0;
                ph[2 * half + 1] = h1;
                float f00 = __uint_as_float(h0 << 16);
                float f01 = __uint_as_float(h0 & 0xffff0000u);
                float f10 = __uint_as_float(h1 << 16);
                float f11 = __uint_as_float(h1 & 0xffff0000u);
                pl[2 * half]     = pack_bf16(sp0[0] - f00, sp0[1] - f01);
                pl[2 * half + 1] = pack_bf16(sp0[2] - f10, sp0[3] - f11);
            }
            // reorder: A frag = {blk0 row r, blk0 row r+8, blk1 row r, blk1 row r+8}
            uint32_t pa_h[4] = {ph[0], ph[1], ph[2], ph[3]};
            uint32_t pa_l[4] = {pl[0], pl[1], pl[2], pl[3]};
#pragma unroll
            for (int nb2 = 0; nb2 < 8; nb2++) {
                int nrow = nb2 * 16 + brow_base;
                uint32_t vad = sb + 32768 + nrow * 128 +
                               ((uint32_t)((kc2 * 2 + bKh) ^ (nrow & 7)) << 4);
                uint32_t vh[4], vl[4];
                ldsm4(vh, vad);
                ldsm4(vl, vad + 16384);
                mma16816(acc_o[2 * nb2],     pa_h, vh);
                mma16816(acc_o[2 * nb2 + 1], pa_h, vh + 2);
                mma16816(acc_o[2 * nb2],     pa_l, vh);
                mma16816(acc_o[2 * nb2 + 1], pa_l, vh + 2);
                mma16816(acc_o[2 * nb2],     pa_h, vl);
                mma16816(acc_o[2 * nb2 + 1], pa_h, vl + 2);
            }
        }
        __syncthreads();
    }

    // ---- epilogue: normalize, split to bf16 hi/lo, write [b, s, h*128+d] ----
    float rl[2] = {1.0f / lsum[0], 1.0f / lsum[1]};
    const int r0 = lane >> 2;
    const int c0 = (lane & 3) << 1;
#pragma unroll
    for (int nb = 0; nb < 16; nb++) {
#pragma unroll
        for (int r2 = 0; r2 < 2; r2++) {
            float v0 = acc_o[nb][2 * r2] * rl[r2];
            float v1 = acc_o[nb][2 * r2 + 1] * rl[r2];
            uint32_t hp = pack_bf16(v0, v1);
            float h0 = __uint_as_float(hp << 16);
            float h1 = __uint_as_float(hp & 0xffff0000u);
            uint32_t lp = pack_bf16(v0 - h0, v1 - h1);
            int gr = q0 + wm * 16 + r0 + r2 * 8;
            int gc = h * 128 + nb * 8 + c0;
            size_t pidx = (((size_t)b * 2048 + gr) * 2048 + gc) >> 1;
            ((uint32_t*)g_AOh)[pidx] = hp;
            ((uint32_t*)g_AOl)[pidx] = lp;
        }
    }
}

// ---------------------------------------------------------------------------
extern "C" void kernel_launch(void* const* d_in, const int* in_sizes, int n_in,
                              void* d_out, int out_size)
{
    const float* q  = (const float*)d_in[0];
    const float* k  = (const float*)d_in[1];
    const float* v  = (const float*)d_in[2];
    const float* Wq = (const float*)d_in[3];
    const float* bq = (const float*)d_in[4];
    const float* Wk = (const float*)d_in[5];
    const float* bk = (const float*)d_in[6];
    const float* Wv = (const float*)d_in[7];
    const float* bv = (const float*)d_in[8];
    const float* Wo = (const float*)d_in[9];
    const float* bo = (const float*)d_in[10];
    const int* mask = (const int*)d_in[11];
    float* out = (float*)d_out;

    __nv_bfloat16 *pINh, *pINl, *pWh, *pWl, *pPh, *pPl, *pVTh, *pVTl, *pAOh, *pAOl;
    cudaGetSymbolAddress((void**)&pINh, g_INh);
    cudaGetSymbolAddress((void**)&pINl, g_INl);
    cudaGetSymbolAddress((void**)&pWh,  g_Wh);
    cudaGetSymbolAddress((void**)&pWl,  g_Wl);
    cudaGetSymbolAddress((void**)&pPh,  g_Ph);
    cudaGetSymbolAddress((void**)&pPl,  g_Pl);
    cudaGetSymbolAddress((void**)&pVTh, g_VTh);
    cudaGetSymbolAddress((void**)&pVTl, g_VTl);
    cudaGetSymbolAddress((void**)&pAOh, g_AOh);
    cudaGetSymbolAddress((void**)&pAOl, g_AOl);

    cudaFuncSetAttribute(flash_attn, cudaFuncAttributeMaxDynamicSharedMemorySize,
                         FA_SMEM);
    cudaFuncSetAttribute(gemm_mma, cudaFuncAttributeMaxDynamicSharedMemorySize,
                         GEMM_SMEM);

    conv_split<<<8192, 256>>>((const float4*)q, pINh + 0 * MK, pINl + 0 * MK, MK / 4);
    conv_split<<<8192, 256>>>((const float4*)k, pINh + 1 * MK, pINl + 1 * MK, MK / 4);
    conv_split<<<8192, 256>>>((const float4*)v, pINh + 2 * MK, pINl + 2 * MK, MK / 4);
    conv_split<<<4096, 256>>>((const float4*)Wq, pWh + 0 * KN, pWl + 0 * KN, KN / 4);
    conv_split<<<4096, 256>>>((const float4*)Wk, pWh + 1 * KN, pWl + 1 * KN, KN / 4);
    conv_split<<<4096, 256>>>((const float4*)Wv, pWh + 2 * KN, pWl + 2 * KN, KN / 4);
    conv_split<<<4096, 256>>>((const float4*)Wo, pWh + 3 * KN, pWl + 3 * KN, KN / 4);

    // Q/K/V projections -> bf16 hi/lo directly
    dim3 gqkv(NDIM / GBN, M_ROWS / GBM, 3);
    gemm_mma<<<gqkv, 256, GEMM_SMEM>>>(pINh, pINl, pWh, pWl, bq, bk, bv,
                                       nullptr, pPh, pPl, MK, KN);

    // V -> V^T
    dim3 gt(64, 64, NB);
    transpose_v<<<gt, dim3(32, 8)>>>(pPh + 2 * MK, pPl + 2 * MK, pVTh, pVTl);

    // attention (tensor cores)
    dim3 ga(S_LEN / 128, NH, NB);            // (16, 16, 2)
    flash_attn<<<ga, 256, FA_SMEM>>>(mask);

    // O projection -> fp32 out
    dim3 go(NDIM / GBN, M_ROWS / GBM, 1);
    gemm_mma<<<go, 256, GEMM_SMEM>>>(pAOh, pAOl, pWh + 3 * KN, pWl + 3 * KN,
                                     bo, bo, bo, out, nullptr, nullptr, 0, 0);
}